// round 9
// baseline (speedup 1.0000x reference)
#include <cuda_runtime.h>
#include <cstddef>

#define NS 2000
#define NG 10000
#define NE 30000          // NG * 3 gradient entries
#define NSOAP 6144

struct Ptrs { const float* v[6]; const float* g[6]; };

__constant__ float FAC[6] = {
    1.0f,
    0.5773502691896258f,   // 1/sqrt(3)
    0.4472135954999579f,   // 1/sqrt(5)
    0.3779644730092272f,   // 1/sqrt(7)
    0.3333333333333333f,   // 1/sqrt(9)
    0.30151134457776363f   // 1/sqrt(11)
};

typedef unsigned long long u64;

__device__ __forceinline__ u64 fma2(u64 a, u64 b, u64 c) {
    u64 d;
    asm("fma.rn.f32x2 %0, %1, %2, %3;" : "=l"(d) : "l"(a), "l"(b), "l"(c));
    return d;
}
__device__ __forceinline__ u64 mul2(u64 a, u64 b) {
    u64 d;
    asm("mul.rn.f32x2 %0, %1, %2;" : "=l"(d) : "l"(a), "l"(b));
    return d;
}
__device__ __forceinline__ u64 dup2(float x) {
    u64 d;
    asm("mov.b64 %0, {%1, %1};" : "=l"(d) : "f"(x));
    return d;
}
union U64F2 { u64 u; float2 f; };

// ---------------------------------------------------------------------------
// grads tile, direct-from-global:
//   T[a,b] = fac * sum_m ( g[m,a]*v[m,b] + v[m,a]*g[m,b] )
// lane = 8 rows x 4 cols; rows packed pairwise into f32x2 accumulators.
// fac applied once to accumulators at store.
// ---------------------------------------------------------------------------
__device__ __forceinline__ void grads_tile(const float* __restrict__ gb,
                                           const float* __restrict__ vb,
                                           int M, int a0, int b0, float fac,
                                           float* __restrict__ o) {
    u64 acc[4][4];
#pragma unroll
    for (int r = 0; r < 4; ++r)
#pragma unroll
        for (int c = 0; c < 4; ++c) acc[r][c] = 0ull;

    for (int m = 0; m < M; ++m) {
        const float* rg = gb + m * 32;
        const float* rv = vb + m * 32;
        // g: streamed (read-once globally) -> evict-first
        ulonglong2 gA = __ldcs((const ulonglong2*)(rg + a0));
        ulonglong2 gB = __ldcs((const ulonglong2*)(rg + a0 + 4));
        float4 gc4 = __ldcs((const float4*)(rg + b0));
        // v: gathered, reused across blocks -> keep in L2
        ulonglong2 vA = *(const ulonglong2*)(rv + a0);
        ulonglong2 vB = *(const ulonglong2*)(rv + a0 + 4);
        float4 vc4 = *(const float4*)(rv + b0);

        u64 ga2[4] = {gA.x, gA.y, gB.x, gB.y};
        u64 va2[4] = {vA.x, vA.y, vB.x, vB.y};
        u64 gd[4] = {dup2(gc4.x), dup2(gc4.y), dup2(gc4.z), dup2(gc4.w)};
        u64 vd[4] = {dup2(vc4.x), dup2(vc4.y), dup2(vc4.z), dup2(vc4.w)};
#pragma unroll
        for (int r = 0; r < 4; ++r)
#pragma unroll
            for (int c = 0; c < 4; ++c) {
                acc[r][c] = fma2(ga2[r], vd[c], acc[r][c]);
                acc[r][c] = fma2(va2[r], gd[c], acc[r][c]);
            }
    }

    const u64 f2 = dup2(fac);
#pragma unroll
    for (int r = 0; r < 4; ++r) {
        U64F2 u0, u1, u2, u3;
        u0.u = mul2(acc[r][0], f2); u1.u = mul2(acc[r][1], f2);
        u2.u = mul2(acc[r][2], f2); u3.u = mul2(acc[r][3], f2);
        float4 lo = make_float4(u0.f.x, u1.f.x, u2.f.x, u3.f.x);
        float4 hi = make_float4(u0.f.y, u1.f.y, u2.f.y, u3.f.y);
        float* orow = o + (a0 + 2 * r) * 32 + b0;
        __stcs((float4*)orow, lo);
        __stcs((float4*)(orow + 32), hi);
    }
}

// ---------------------------------------------------------------------------
// values tile, direct-from-global: T[a,b] = fac * sum_m v[m,a]*v[m,b]
// ---------------------------------------------------------------------------
__device__ __forceinline__ void values_tile(const float* __restrict__ base,
                                            int M, float fac, int a0, int b0,
                                            float* __restrict__ o) {
    float acc[8][4];
#pragma unroll
    for (int r = 0; r < 8; ++r)
#pragma unroll
        for (int c = 0; c < 4; ++c) acc[r][c] = 0.0f;

    for (int m = 0; m < M; ++m) {
        const float* row = base + m * 32;
        float4 a0v = *(const float4*)(row + a0);
        float4 a1v = *(const float4*)(row + a0 + 4);
        float4 bv  = *(const float4*)(row + b0);
        float av[8] = {a0v.x, a0v.y, a0v.z, a0v.w, a1v.x, a1v.y, a1v.z, a1v.w};
        float bb[4] = {bv.x, bv.y, bv.z, bv.w};
#pragma unroll
        for (int r = 0; r < 8; ++r)
#pragma unroll
            for (int c = 0; c < 4; ++c) acc[r][c] += av[r] * bb[c];
    }

#pragma unroll
    for (int r = 0; r < 8; ++r) {
        float4 s = make_float4(fac * acc[r][0], fac * acc[r][1],
                               fac * acc[r][2], fac * acc[r][3]);
        __stcs((float4*)(o + (a0 + r) * 32 + b0), s);
    }
}

// ---------------------------------------------------------------------------
// fused kernel: 96 threads (3 warps), NO shared memory, NO barriers.
//   bid <  NE : gradient entry e = bid
//   bid >= NE : values sample i = bid - NE
// warp k handles l = 5-k then l = k  ->  12 m-steps per warp (balanced).
// ---------------------------------------------------------------------------
__global__ void __launch_bounds__(96, 10) fused_kernel(Ptrs p,
                                                       const int* __restrict__ gidx,
                                                       float* __restrict__ out) {
    const int bid = blockIdx.x;
    const int tid = threadIdx.x;
    const int k = tid >> 5;
    const int lane = tid & 31;
    const int a0 = (lane >> 3) * 8;
    const int b0 = (lane & 7) * 4;

    if (bid < NE) {
        const int e = bid;
        const int s = __ldg(gidx + e / 3);
        float* obase = out + (size_t)NS * NSOAP + (size_t)e * NSOAP;
        {
            const int l = 5 - k;
            const int M = 2 * l + 1;
            grads_tile(p.g[l] + (size_t)e * M * 32,
                       p.v[l] + (size_t)s * M * 32,
                       M, a0, b0, FAC[l], obase + l * 1024);
        }
        {
            const int l = k;
            const int M = 2 * l + 1;
            grads_tile(p.g[l] + (size_t)e * M * 32,
                       p.v[l] + (size_t)s * M * 32,
                       M, a0, b0, FAC[l], obase + l * 1024);
        }
    } else {
        const int i = bid - NE;
        float* obase = out + (size_t)i * NSOAP;
        {
            const int l = 5 - k;
            const int M = 2 * l + 1;
            values_tile(p.v[l] + (size_t)i * M * 32, M, FAC[l], a0, b0,
                        obase + l * 1024);
        }
        {
            const int l = k;
            const int M = 2 * l + 1;
            values_tile(p.v[l] + (size_t)i * M * 32, M, FAC[l], a0, b0,
                        obase + l * 1024);
        }
    }
}

// ---------------------------------------------------------------------------
extern "C" void kernel_launch(void* const* d_in, const int* in_sizes, int n_in,
                              void* d_out, int out_size) {
    Ptrs p;
    const int* gidx = nullptr;
    for (int k = 0; k < n_in; ++k) {
        const int sz = in_sizes[k];
        if (sz == NG) { gidx = (const int*)d_in[k]; continue; }
        for (int l = 0; l < 6; ++l) {
            const int M = 2 * l + 1;
            if (sz == NS * M * 32)          p.v[l] = (const float*)d_in[k];
            else if (sz == NG * 3 * M * 32) p.g[l] = (const float*)d_in[k];
        }
    }
    float* out = (float*)d_out;

    fused_kernel<<<NE + NS, 96>>>(p, gidx, out);
    (void)out_size;
}

// round 10
// speedup vs baseline: 1.7474x; 1.7474x over previous
#include <cuda_runtime.h>
#include <cstddef>

#define NS 2000
#define NG 10000
#define NE 30000          // NG * 3 gradient entries
#define NSOAP 6144

struct Ptrs { const float* v[6]; const float* g[6]; };

__constant__ float FAC[6] = {
    1.0f,
    0.5773502691896258f,   // 1/sqrt(3)
    0.4472135954999579f,   // 1/sqrt(5)
    0.3779644730092272f,   // 1/sqrt(7)
    0.3333333333333333f,   // 1/sqrt(9)
    0.30151134457776363f   // 1/sqrt(11)
};

// smem offset for l-block: sum_{l'<l} (2l'+1)*32 = 32*l*l
__device__ __forceinline__ int loff(int l) { return 32 * l * l; }

typedef unsigned long long u64;

__device__ __forceinline__ u64 fma2(u64 a, u64 b, u64 c) {
    u64 d;
    asm("fma.rn.f32x2 %0, %1, %2, %3;" : "=l"(d) : "l"(a), "l"(b), "l"(c));
    return d;
}
__device__ __forceinline__ u64 mul2(u64 a, u64 b) {
    u64 d;
    asm("mul.rn.f32x2 %0, %1, %2;" : "=l"(d) : "l"(a), "l"(b));
    return d;
}
__device__ __forceinline__ u64 dup2(float x) {
    u64 d;
    asm("mov.b64 %0, {%1, %1};" : "=l"(d) : "f"(x));
    return d;
}
union U64F2 { u64 u; float2 f; };

__device__ __forceinline__ void cp16(void* smem_dst, const void* gmem_src) {
    unsigned saddr = (unsigned)__cvta_generic_to_shared(smem_dst);
    asm volatile("cp.async.cg.shared.global [%0], [%1], 16;"
                 :: "r"(saddr), "l"(gmem_src) : "memory");
}
__device__ __forceinline__ void cp_commit_wait() {
    asm volatile("cp.async.commit_group;" ::: "memory");
    asm volatile("cp.async.wait_group 0;" ::: "memory");
}

// ---------------------------------------------------------------------------
// grads tile: T[a,b] = fac * sum_m ( g[m,a]*v[m,b] + v[m,a]*g[m,b] )
// lane = 8 rows x 4 cols; rows packed pairwise into f32x2 accumulators.
// fac applied once at epilogue (v staged unscaled).
// ---------------------------------------------------------------------------
__device__ __forceinline__ void grads_tile(const float* __restrict__ gb,
                                           const float* __restrict__ vb,
                                           int M, int a0, int b0, float fac,
                                           float* __restrict__ o) {
    u64 acc[4][4];
#pragma unroll
    for (int r = 0; r < 4; ++r)
#pragma unroll
        for (int c = 0; c < 4; ++c) acc[r][c] = 0ull;

    for (int m = 0; m < M; ++m) {
        const float* rg = gb + m * 32;
        const float* rv = vb + m * 32;
        ulonglong2 gA = *(const ulonglong2*)(rg + a0);
        ulonglong2 gB = *(const ulonglong2*)(rg + a0 + 4);
        ulonglong2 vA = *(const ulonglong2*)(rv + a0);
        ulonglong2 vB = *(const ulonglong2*)(rv + a0 + 4);
        u64 ga2[4] = {gA.x, gA.y, gB.x, gB.y};
        u64 va2[4] = {vA.x, vA.y, vB.x, vB.y};
        float4 gc4 = *(const float4*)(rg + b0);
        float4 vc4 = *(const float4*)(rv + b0);
        u64 gd[4] = {dup2(gc4.x), dup2(gc4.y), dup2(gc4.z), dup2(gc4.w)};
        u64 vd[4] = {dup2(vc4.x), dup2(vc4.y), dup2(vc4.z), dup2(vc4.w)};
#pragma unroll
        for (int r = 0; r < 4; ++r)
#pragma unroll
            for (int c = 0; c < 4; ++c) {
                acc[r][c] = fma2(ga2[r], vd[c], acc[r][c]);
                acc[r][c] = fma2(va2[r], gd[c], acc[r][c]);
            }
    }

    const u64 f2 = dup2(fac);
#pragma unroll
    for (int r = 0; r < 4; ++r) {
        U64F2 u0, u1, u2, u3;
        u0.u = mul2(acc[r][0], f2); u1.u = mul2(acc[r][1], f2);
        u2.u = mul2(acc[r][2], f2); u3.u = mul2(acc[r][3], f2);
        float4 lo = make_float4(u0.f.x, u1.f.x, u2.f.x, u3.f.x);
        float4 hi = make_float4(u0.f.y, u1.f.y, u2.f.y, u3.f.y);
        float* orow = o + (a0 + 2 * r) * 32 + b0;
        __stcs((float4*)orow, lo);
        __stcs((float4*)(orow + 32), hi);
    }
}

// ---------------------------------------------------------------------------
// values tile: T[a,b] = fac * sum_m v[m,a]*v[m,b]   (lane = 8x4)
// ---------------------------------------------------------------------------
__device__ __forceinline__ void values_tile(const float* __restrict__ base,
                                            int M, float fac, int a0, int b0,
                                            float* __restrict__ o) {
    float acc[8][4];
#pragma unroll
    for (int r = 0; r < 8; ++r)
#pragma unroll
        for (int c = 0; c < 4; ++c) acc[r][c] = 0.0f;

    for (int m = 0; m < M; ++m) {
        const float* row = base + m * 32;
        float4 a0v = *(const float4*)(row + a0);
        float4 a1v = *(const float4*)(row + a0 + 4);
        float4 bv  = *(const float4*)(row + b0);
        float av[8] = {a0v.x, a0v.y, a0v.z, a0v.w, a1v.x, a1v.y, a1v.z, a1v.w};
        float bb[4] = {bv.x, bv.y, bv.z, bv.w};
#pragma unroll
        for (int r = 0; r < 8; ++r)
#pragma unroll
            for (int c = 0; c < 4; ++c) acc[r][c] += av[r] * bb[c];
    }

#pragma unroll
    for (int r = 0; r < 8; ++r) {
        float4 s = make_float4(fac * acc[r][0], fac * acc[r][1],
                               fac * acc[r][2], fac * acc[r][3]);
        __stcs((float4*)(o + (a0 + r) * 32 + b0), s);
    }
}

// ---------------------------------------------------------------------------
// fused kernel: 96 threads (3 warps) per block, cp.async staging.
//   bid <  NE : gradient entry e = bid
//   bid >= NE : values sample i = bid - NE
// warp k handles l = 5-k then l = k  ->  12 m-steps per warp (balanced).
// ---------------------------------------------------------------------------
__global__ void __launch_bounds__(96, 10) fused_kernel(Ptrs p,
                                                       const int* __restrict__ gidx,
                                                       float* __restrict__ out) {
    __shared__ __align__(16) float sA[1152];   // g (grads) / v (values)
    __shared__ __align__(16) float sB[1152];   // v (grads, unscaled)
    const int bid = blockIdx.x;
    const int tid = threadIdx.x;
    const int k = tid >> 5;
    const int lane = tid & 31;
    const int a0 = (lane >> 3) * 8;
    const int b0 = (lane & 7) * 4;

    if (bid < NE) {
        const int e = bid;
        const int s = __ldg(gidx + e / 3);
#pragma unroll
        for (int l = 0; l < 6; ++l) {
            const int cnt4 = (2 * l + 1) * 8;
            const float4* gs = (const float4*)(p.g[l] + (size_t)e * (2 * l + 1) * 32);
            const float4* vs = (const float4*)(p.v[l] + (size_t)s * (2 * l + 1) * 32);
            float4* dg = (float4*)(sA + loff(l));
            float4* dv = (float4*)(sB + loff(l));
            for (int j = tid; j < cnt4; j += 96) {
                cp16(dg + j, gs + j);
                cp16(dv + j, vs + j);
            }
        }
        cp_commit_wait();
        __syncthreads();

        float* obase = out + (size_t)NS * NSOAP + (size_t)e * NSOAP;
        {
            const int l = 5 - k;
            grads_tile(sA + loff(l), sB + loff(l), 2 * l + 1, a0, b0, FAC[l],
                       obase + l * 1024);
        }
        {
            const int l = k;
            grads_tile(sA + loff(l), sB + loff(l), 2 * l + 1, a0, b0, FAC[l],
                       obase + l * 1024);
        }
    } else {
        const int i = bid - NE;
#pragma unroll
        for (int l = 0; l < 6; ++l) {
            const int cnt4 = (2 * l + 1) * 8;
            const float4* src = (const float4*)(p.v[l] + (size_t)i * (2 * l + 1) * 32);
            float4* dst = (float4*)(sA + loff(l));
            for (int j = tid; j < cnt4; j += 96) cp16(dst + j, src + j);
        }
        cp_commit_wait();
        __syncthreads();

        float* obase = out + (size_t)i * NSOAP;
        {
            const int l = 5 - k;
            values_tile(sA + loff(l), 2 * l + 1, FAC[l], a0, b0, obase + l * 1024);
        }
        {
            const int l = k;
            values_tile(sA + loff(l), 2 * l + 1, FAC[l], a0, b0, obase + l * 1024);
        }
    }
}

// ---------------------------------------------------------------------------
extern "C" void kernel_launch(void* const* d_in, const int* in_sizes, int n_in,
                              void* d_out, int out_size) {
    Ptrs p;
    const int* gidx = nullptr;
    for (int k = 0; k < n_in; ++k) {
        const int sz = in_sizes[k];
        if (sz == NG) { gidx = (const int*)d_in[k]; continue; }
        for (int l = 0; l < 6; ++l) {
            const int M = 2 * l + 1;
            if (sz == NS * M * 32)          p.v[l] = (const float*)d_in[k];
            else if (sz == NG * 3 * M * 32) p.g[l] = (const float*)d_in[k];
        }
    }
    float* out = (float*)d_out;

    fused_kernel<<<NE + NS, 96>>>(p, gidx, out);
    (void)out_size;
}